// round 1
// baseline (speedup 1.0000x reference)
#include <cuda_runtime.h>
#include <math.h>

// Problem shape (fixed for this dataset entry)
#define BB 4
#define SS 2048
#define DD 1024
#define HH 16
#define DH 64
#define MROWS (BB*SS)   // 8192

// Scratch (allocation-free rule: __device__ globals)
__device__ float g_q[(size_t)BB*HH*SS*DH];
__device__ float g_k[(size_t)BB*HH*SS*DH];
__device__ float g_v[(size_t)BB*HH*SS*DH];
__device__ float g_attn[(size_t)MROWS*DD];

// ---------------------------------------------------------------------------
// Tiled fp32 GEMM: C[M,N] = A[M,K] @ W[K,N] + bias[N]
// BM=128, BN=128, BK=16, 256 threads, 8x8 per thread.
// SCATTER=1: write into (B,H,S,Dh) layout; SCATTER=0: row-major [M,N].
// ---------------------------------------------------------------------------
template<int SCATTER>
__device__ __forceinline__ void gemm_body(const float* __restrict__ A,
                                          const float* __restrict__ W,
                                          const float* __restrict__ bias,
                                          float* __restrict__ C)
{
    __shared__ float As[16][132];   // [k][m] (transposed)
    __shared__ float Bs[16][132];   // [k][n]
    const int K = DD, N = DD;
    const int tid = threadIdx.x;
    const int tx = tid & 15, ty = tid >> 4;
    const int m0 = blockIdx.y * 128;
    const int n0 = blockIdx.x * 128;

    float acc[8][8];
    #pragma unroll
    for (int i = 0; i < 8; ++i)
        #pragma unroll
        for (int j = 0; j < 8; ++j) acc[i][j] = 0.f;

    for (int k0 = 0; k0 < K; k0 += 16) {
        // Load A tile (128x16) transposed into As[k][m]
        #pragma unroll
        for (int it = 0; it < 2; ++it) {
            int idx = tid + it * 256;        // 0..511
            int row = idx >> 2;              // 0..127
            int seg = (idx & 3) * 4;         // 0,4,8,12
            float4 v = *(const float4*)(A + (size_t)(m0 + row) * K + k0 + seg);
            As[seg + 0][row] = v.x;
            As[seg + 1][row] = v.y;
            As[seg + 2][row] = v.z;
            As[seg + 3][row] = v.w;
        }
        // Load W tile (16x128) direct into Bs[k][n]
        #pragma unroll
        for (int it = 0; it < 2; ++it) {
            int idx = tid + it * 256;        // 0..511
            int row = idx >> 5;              // 0..15
            int c4  = (idx & 31) * 4;        // 0..124
            *(float4*)&Bs[row][c4] =
                *(const float4*)(W + (size_t)(k0 + row) * N + n0 + c4);
        }
        __syncthreads();

        #pragma unroll
        for (int k = 0; k < 16; ++k) {
            float a[8], b[8];
            #pragma unroll
            for (int i = 0; i < 8; ++i) a[i] = As[k][ty * 8 + i];
            #pragma unroll
            for (int j = 0; j < 8; ++j) b[j] = Bs[k][tx * 8 + j];
            #pragma unroll
            for (int i = 0; i < 8; ++i)
                #pragma unroll
                for (int j = 0; j < 8; ++j)
                    acc[i][j] = fmaf(a[i], b[j], acc[i][j]);
        }
        __syncthreads();
    }

    #pragma unroll
    for (int i = 0; i < 8; ++i) {
        int m = m0 + ty * 8 + i;
        #pragma unroll
        for (int j = 0; j < 8; ++j) {
            int n = n0 + tx * 8 + j;
            float v = acc[i][j] + bias[n];
            if (SCATTER) {
                int b = m >> 11;           // m / S
                int s = m & (SS - 1);
                int h = n >> 6;            // n / Dh
                int d = n & (DH - 1);
                C[(((size_t)(b * HH + h)) * SS + s) * DH + d] = v;
            } else {
                C[(size_t)m * N + n] = v;
            }
        }
    }
}

__global__ void __launch_bounds__(256)
qkv_proj_kernel(const float* __restrict__ X,
                const float* __restrict__ Wq, const float* __restrict__ bq,
                const float* __restrict__ Wk, const float* __restrict__ bk,
                const float* __restrict__ Wv, const float* __restrict__ bv)
{
    int z = blockIdx.z;
    const float* W; const float* bias; float* out;
    if (z == 0)      { W = Wq; bias = bq; out = g_q; }
    else if (z == 1) { W = Wk; bias = bk; out = g_k; }
    else             { W = Wv; bias = bv; out = g_v; }
    gemm_body<1>(X, W, bias, out);
}

__global__ void __launch_bounds__(256)
out_proj_kernel(const float* __restrict__ Wo, const float* __restrict__ bo,
                float* __restrict__ out)
{
    gemm_body<0>(g_attn, Wo, bo, out);
}

// ---------------------------------------------------------------------------
// Flash-style causal attention.
// Grid: (S/64, B*H). Block: 256 threads. 64 query rows x 64 kv rows per tile.
// Score phase: 16x16 thread grid, 4x4 microtile. Softmax/O phase: 4 thr/row,
// 16 output cols per thread. Online softmax with running (m, l).
// ---------------------------------------------------------------------------
#define QS_STRIDE 68   // float4-aligned (68*4 % 16 == 0)
#define KT_STRIDE 65   // odd stride: 2-way max conflicts on transposed access
#define VS_STRIDE 68
#define SS_STRIDE 65

__global__ void __launch_bounds__(256)
attn_kernel()
{
    extern __shared__ float sm[];
    float* Qs  = sm;                        // [64][QS_STRIDE]  Q[r][d]
    float* KsT = Qs  + 64 * QS_STRIDE;      // [64][KT_STRIDE]  K^T[d][j]
    float* Vs  = KsT + 64 * KT_STRIDE;      // [64][VS_STRIDE]  V[j][c]
    float* Sc  = Vs  + 64 * VS_STRIDE;      // [64][SS_STRIDE]  scores / probs

    const int tid = threadIdx.x;
    const int bh  = blockIdx.y;             // 0..63  (b*H + h)
    const int qt  = blockIdx.x;             // 0..31
    const int q0  = qt * 64;

    const float* Qp = g_q + (size_t)bh * SS * DH;
    const float* Kp = g_k + (size_t)bh * SS * DH;
    const float* Vp = g_v + (size_t)bh * SS * DH;

    // score-phase mapping
    const int stx = (tid & 15) * 4;         // col base
    const int sty = (tid >> 4) * 4;         // row base
    // softmax/O-phase mapping
    const int r  = tid >> 2;                // query row 0..63
    const int gc = (tid & 3) * 16;          // col base (16 cols per thread)

    // Load Q tile once (64x64)
    #pragma unroll
    for (int it = 0; it < 4; ++it) {
        int idx = tid + it * 256;           // 0..1023
        int rr = idx >> 4;
        int c4 = (idx & 15) * 4;
        *(float4*)&Qs[rr * QS_STRIDE + c4] =
            *(const float4*)(Qp + (size_t)(q0 + rr) * DH + c4);
    }

    float m_run = -1e30f, l_run = 0.f;
    float o[16];
    #pragma unroll
    for (int i = 0; i < 16; ++i) o[i] = 0.f;

    for (int kt = 0; kt <= qt; ++kt) {
        const int t0 = kt * 64;
        __syncthreads();   // previous iteration's reads of KsT/Vs/Sc done

        // Load K tile transposed, V tile direct
        #pragma unroll
        for (int it = 0; it < 4; ++it) {
            int idx = tid + it * 256;
            int rr  = idx >> 4;             // kv row 0..63
            int c4  = (idx & 15) * 4;       // d base
            float4 kv = *(const float4*)(Kp + (size_t)(t0 + rr) * DH + c4);
            KsT[(c4 + 0) * KT_STRIDE + rr] = kv.x;
            KsT[(c4 + 1) * KT_STRIDE + rr] = kv.y;
            KsT[(c4 + 2) * KT_STRIDE + rr] = kv.z;
            KsT[(c4 + 3) * KT_STRIDE + rr] = kv.w;
            *(float4*)&Vs[rr * VS_STRIDE + c4] =
                *(const float4*)(Vp + (size_t)(t0 + rr) * DH + c4);
        }
        __syncthreads();

        // Score tile: S = Q @ K^T   (4x4 per thread)
        {
            float acc[4][4];
            #pragma unroll
            for (int i = 0; i < 4; ++i)
                #pragma unroll
                for (int j = 0; j < 4; ++j) acc[i][j] = 0.f;

            #pragma unroll 4
            for (int d = 0; d < 64; ++d) {
                float a[4], b[4];
                #pragma unroll
                for (int i = 0; i < 4; ++i) a[i] = Qs[(sty + i) * QS_STRIDE + d];
                #pragma unroll
                for (int j = 0; j < 4; ++j) b[j] = KsT[d * KT_STRIDE + stx + j];
                #pragma unroll
                for (int i = 0; i < 4; ++i)
                    #pragma unroll
                    for (int j = 0; j < 4; ++j)
                        acc[i][j] = fmaf(a[i], b[j], acc[i][j]);
            }
            #pragma unroll
            for (int i = 0; i < 4; ++i)
                #pragma unroll
                for (int j = 0; j < 4; ++j)
                    Sc[(sty + i) * SS_STRIDE + stx + j] = acc[i][j];
        }
        __syncthreads();

        // Online softmax update (4 threads per row, 16 cols each)
        {
            float sv[16];
            float mloc = -1e30f;
            #pragma unroll
            for (int cc = 0; cc < 16; ++cc) {
                int j = gc + cc;
                float s = Sc[r * SS_STRIDE + j] * 0.125f;   // 1/sqrt(64)
                if (t0 + j > q0 + r) s = -1e30f;            // causal mask
                sv[cc] = s;
                mloc = fmaxf(mloc, s);
            }
            // reduce max over the 4-lane group (lane-aligned groups)
            mloc = fmaxf(mloc, __shfl_xor_sync(0xffffffffu, mloc, 1));
            mloc = fmaxf(mloc, __shfl_xor_sync(0xffffffffu, mloc, 2));

            float m_new = fmaxf(m_run, mloc);
            float corr  = __expf(m_run - m_new);
            float psum  = 0.f;
            #pragma unroll
            for (int cc = 0; cc < 16; ++cc) {
                float p = __expf(sv[cc] - m_new);
                Sc[r * SS_STRIDE + gc + cc] = p;
                psum += p;
            }
            psum += __shfl_xor_sync(0xffffffffu, psum, 1);
            psum += __shfl_xor_sync(0xffffffffu, psum, 2);

            l_run = l_run * corr + psum;
            m_run = m_new;
            #pragma unroll
            for (int cc = 0; cc < 16; ++cc) o[cc] *= corr;
        }
        __syncthreads();

        // O += P @ V   (thread owns row r, cols gc..gc+15)
        #pragma unroll 2
        for (int j = 0; j < 64; ++j) {
            float p = Sc[r * SS_STRIDE + j];
            const float* vrow = &Vs[j * VS_STRIDE + gc];
            float4 v0 = *(const float4*)(vrow + 0);
            float4 v1 = *(const float4*)(vrow + 4);
            float4 v2 = *(const float4*)(vrow + 8);
            float4 v3 = *(const float4*)(vrow + 12);
            o[0]  = fmaf(p, v0.x, o[0]);  o[1]  = fmaf(p, v0.y, o[1]);
            o[2]  = fmaf(p, v0.z, o[2]);  o[3]  = fmaf(p, v0.w, o[3]);
            o[4]  = fmaf(p, v1.x, o[4]);  o[5]  = fmaf(p, v1.y, o[5]);
            o[6]  = fmaf(p, v1.z, o[6]);  o[7]  = fmaf(p, v1.w, o[7]);
            o[8]  = fmaf(p, v2.x, o[8]);  o[9]  = fmaf(p, v2.y, o[9]);
            o[10] = fmaf(p, v2.z, o[10]); o[11] = fmaf(p, v2.w, o[11]);
            o[12] = fmaf(p, v3.x, o[12]); o[13] = fmaf(p, v3.y, o[13]);
            o[14] = fmaf(p, v3.z, o[14]); o[15] = fmaf(p, v3.w, o[15]);
        }
    }

    // Write normalized output into (B, S, D) layout for the output projection
    {
        float inv = 1.f / l_run;
        int b = bh >> 4;            // bh / H
        int h = bh & (HH - 1);
        size_t base = ((size_t)(b * SS + q0 + r)) * DD + h * DH + gc;
        float4 w0 = make_float4(o[0] * inv,  o[1] * inv,  o[2] * inv,  o[3] * inv);
        float4 w1 = make_float4(o[4] * inv,  o[5] * inv,  o[6] * inv,  o[7] * inv);
        float4 w2 = make_float4(o[8] * inv,  o[9] * inv,  o[10] * inv, o[11] * inv);
        float4 w3 = make_float4(o[12] * inv, o[13] * inv, o[14] * inv, o[15] * inv);
        *(float4*)&g_attn[base + 0]  = w0;
        *(float4*)&g_attn[base + 4]  = w1;
        *(float4*)&g_attn[base + 8]  = w2;
        *(float4*)&g_attn[base + 12] = w3;
    }
}

// ---------------------------------------------------------------------------
extern "C" void kernel_launch(void* const* d_in, const int* in_sizes, int n_in,
                              void* d_out, int out_size)
{
    const float* x  = (const float*)d_in[0];
    const float* Wq = (const float*)d_in[1];
    const float* bq = (const float*)d_in[2];
    const float* Wk = (const float*)d_in[3];
    const float* bk = (const float*)d_in[4];
    const float* Wv = (const float*)d_in[5];
    const float* bv = (const float*)d_in[6];
    const float* Wo = (const float*)d_in[7];
    const float* bo = (const float*)d_in[8];
    float* out = (float*)d_out;

    // 1) QKV projections (fused over gridDim.z)
    {
        dim3 grid(DD / 128, MROWS / 128, 3);
        qkv_proj_kernel<<<grid, 256>>>(x, Wq, bq, Wk, bk, Wv, bv);
    }

    // 2) Causal attention
    {
        int smem = (64 * QS_STRIDE + 64 * KT_STRIDE +
                    64 * VS_STRIDE + 64 * SS_STRIDE) * (int)sizeof(float);
        static bool attr_set = false;
        if (!attr_set) {
            cudaFuncSetAttribute(attn_kernel,
                                 cudaFuncAttributeMaxDynamicSharedMemorySize, smem);
            attr_set = true;
        }
        dim3 grid(SS / 64, BB * HH);
        attn_kernel<<<grid, 256, smem>>>();
    }

    // 3) Output projection
    {
        dim3 grid(DD / 128, MROWS / 128);
        out_proj_kernel<<<grid, 256>>>(Wo, bo, out);
    }
}

// round 3
// speedup vs baseline: 1.2451x; 1.2451x over previous
#include <cuda_runtime.h>
#include <cuda_bf16.h>
#include <cstdint>
#include <math.h>

// Problem shape (fixed)
#define BB 4
#define SS 2048
#define DD 1024
#define HH 16
#define DH 64
#define MROWS (BB*SS)   // 8192

// ---------------------------------------------------------------------------
// Scratch (__device__ globals; allocation-free rule)
// ---------------------------------------------------------------------------
__device__ float g_q[(size_t)BB*HH*SS*DH];
__device__ float g_k[(size_t)BB*HH*SS*DH];
__device__ float g_v[(size_t)BB*HH*SS*DH];
__device__ float g_attn[(size_t)MROWS*DD];

__device__ __nv_bfloat16 g_x_hi[(size_t)MROWS*DD];
__device__ __nv_bfloat16 g_x_lo[(size_t)MROWS*DD];
__device__ __nv_bfloat16 g_at_hi[(size_t)MROWS*DD];
__device__ __nv_bfloat16 g_at_lo[(size_t)MROWS*DD];
// transposed+split weights: [4][N][K], Wt[n][k] = W[k][n]; 0..3 = q,k,v,o
__device__ __nv_bfloat16 g_wt_hi[(size_t)4*DD*DD];
__device__ __nv_bfloat16 g_wt_lo[(size_t)4*DD*DD];

// ---------------------------------------------------------------------------
// Helpers (base-sm_103-safe: no tcgen05 anywhere)
// ---------------------------------------------------------------------------
__device__ __forceinline__ uint32_t smem_u32(const void* p) {
    uint32_t a;
    asm("{ .reg .u64 t; cvta.to.shared.u64 t, %1; cvt.u32.u64 %0, t; }"
        : "=r"(a) : "l"(p));
    return a;
}
#define CP_ASYNC16(dst_u32, src_ptr) \
    asm volatile("cp.async.cg.shared.global [%0], [%1], 16;" \
                 :: "r"(dst_u32), "l"(src_ptr))
#define CP_COMMIT() asm volatile("cp.async.commit_group;")
#define CP_WAIT1()  asm volatile("cp.async.wait_group 1;")
#define CP_WAIT0()  asm volatile("cp.async.wait_group 0;")

#define LDSM_X4(r0, r1, r2, r3, addr) \
    asm volatile("ldmatrix.sync.aligned.m8n8.x4.shared.b16 {%0,%1,%2,%3}, [%4];" \
                 : "=r"(r0), "=r"(r1), "=r"(r2), "=r"(r3) : "r"(addr))

#define MMA16816(d, a0, a1, a2, a3, b0, b1) \
    asm volatile("mma.sync.aligned.m16n8k16.row.col.f32.bf16.bf16.f32 " \
                 "{%0,%1,%2,%3}, {%4,%5,%6,%7}, {%8,%9}, {%0,%1,%2,%3};" \
                 : "+f"((d)[0]), "+f"((d)[1]), "+f"((d)[2]), "+f"((d)[3]) \
                 : "r"(a0), "r"(a1), "r"(a2), "r"(a3), "r"(b0), "r"(b1))

// ---------------------------------------------------------------------------
// Prep kernels
// ---------------------------------------------------------------------------
__global__ void __launch_bounds__(256)
split_kernel(const float* __restrict__ in, __nv_bfloat16* __restrict__ hi,
             __nv_bfloat16* __restrict__ lo) {
    size_t i = ((size_t)blockIdx.x * 256 + threadIdx.x) * 4;
    float4 v = *(const float4*)(in + i);
    __nv_bfloat16 h0 = __float2bfloat16(v.x);
    __nv_bfloat16 h1 = __float2bfloat16(v.y);
    __nv_bfloat16 h2 = __float2bfloat16(v.z);
    __nv_bfloat16 h3 = __float2bfloat16(v.w);
    __nv_bfloat162 hh0; hh0.x = h0; hh0.y = h1;
    __nv_bfloat162 hh1; hh1.x = h2; hh1.y = h3;
    *(__nv_bfloat162*)(hi + i)     = hh0;
    *(__nv_bfloat162*)(hi + i + 2) = hh1;
    __nv_bfloat162 ll0, ll1;
    ll0.x = __float2bfloat16(v.x - __bfloat162float(h0));
    ll0.y = __float2bfloat16(v.y - __bfloat162float(h1));
    ll1.x = __float2bfloat16(v.z - __bfloat162float(h2));
    ll1.y = __float2bfloat16(v.w - __bfloat162float(h3));
    *(__nv_bfloat162*)(lo + i)     = ll0;
    *(__nv_bfloat162*)(lo + i + 2) = ll1;
}

__global__ void __launch_bounds__(256)
transpose_split_w(const float* __restrict__ Wq, const float* __restrict__ Wk,
                  const float* __restrict__ Wv, const float* __restrict__ Wo) {
    __shared__ float t[32][33];
    const float* W = (blockIdx.z == 0) ? Wq : (blockIdx.z == 1) ? Wk :
                     (blockIdx.z == 2) ? Wv : Wo;
    __nv_bfloat16* Th = g_wt_hi + (size_t)blockIdx.z * DD * DD;
    __nv_bfloat16* Tl = g_wt_lo + (size_t)blockIdx.z * DD * DD;
    int k0 = blockIdx.y * 32, n0 = blockIdx.x * 32;
    int tx = threadIdx.x, ty = threadIdx.y;
    #pragma unroll
    for (int i = ty; i < 32; i += 8)
        t[i][tx] = W[(size_t)(k0 + i) * DD + n0 + tx];
    __syncthreads();
    #pragma unroll
    for (int i = ty; i < 32; i += 8) {
        float v = t[tx][i];               // W[k0+tx][n0+i]
        size_t o = (size_t)(n0 + i) * DD + k0 + tx;
        __nv_bfloat16 h = __float2bfloat16(v);
        Th[o] = h;
        Tl[o] = __float2bfloat16(v - __bfloat162float(h));
    }
}

// ---------------------------------------------------------------------------
// Split-bf16 GEMM on mma.sync (HMMA):
//   C[M,N] = A @ Wt^T + bias,   C ~= Ah*Bh + Ah*Bl + Al*Bh (fp32 accum)
// CTA tile 128x128, BK=32, 8 warps (4M x 2N), warp tile 32x64.
// smem tiles [128 rows][32 k] bf16 with 80B row stride (ldmatrix conflict-free),
// cp.async double-buffered.
// ---------------------------------------------------------------------------
#define KC 32
#define NCHUNK (DD / KC)              // 32
#define ROW_B 80                      // bytes per smem row (32*2 pad to 80)
#define TILE_BY (128 * ROW_B)         // 10240
#define STAGE_BY (4 * TILE_BY)        // 40960
#define SMEM_MMA (2 * STAGE_BY)       // 81920

template<int SCATTER>
__device__ __forceinline__ void mma_gemm_body(const __nv_bfloat16* __restrict__ Ah,
                                              const __nv_bfloat16* __restrict__ Al,
                                              const __nv_bfloat16* __restrict__ Bh,
                                              const __nv_bfloat16* __restrict__ Bl,
                                              const float* __restrict__ bias,
                                              float* __restrict__ C)
{
    extern __shared__ char dynsmem[];
    const uint32_t base_u = smem_u32(dynsmem);

    const int tid  = threadIdx.x;
    const int wid  = tid >> 5, lane = tid & 31;
    const int wm   = wid & 3;          // 0..3  (M)
    const int wn   = wid >> 2;         // 0..1  (N)
    const int m0   = blockIdx.y * 128;
    const int n0   = blockIdx.x * 128;

    const __nv_bfloat16* srcs[4] = { Ah, Al, Bh, Bl };
    const int rowbase[4] = { m0, m0, n0, n0 };

    // cp.async stage issue: 512 16B copies per tile, 2 per thread per tile
    auto issue_stage = [&](int c, int st) {
        #pragma unroll
        for (int tile = 0; tile < 4; ++tile) {
            const __nv_bfloat16* src = srcs[tile] + (size_t)rowbase[tile] * DD + c * KC;
            uint32_t dst = base_u + st * STAGE_BY + tile * TILE_BY;
            #pragma unroll
            for (int it = 0; it < 2; ++it) {
                int idx = tid + it * 256;          // 0..511
                int row = idx >> 2;                // 0..127
                int seg = idx & 3;                 // 0..3 (16B units)
                CP_ASYNC16(dst + row * ROW_B + seg * 16,
                           src + (size_t)row * DD + seg * 8);
            }
        }
    };

    float acc[2][8][4];
    #pragma unroll
    for (int i = 0; i < 2; ++i)
        #pragma unroll
        for (int j = 0; j < 8; ++j)
            #pragma unroll
            for (int q = 0; q < 4; ++q) acc[i][j][q] = 0.f;

    // ldmatrix address components
    const int arow = wm * 32 + (lane & 7) + ((lane >> 3) & 1) * 8;   // + mf*16
    const int akof = ((lane >> 4) & 1) * 16;                          // +ks*32 bytes
    const int brow = wn * 64 + (lane & 7) + ((lane >> 4) & 1) * 8;   // + ng*16
    const int bkof = ((lane >> 3) & 1) * 16;                          // +ks*32 bytes

    issue_stage(0, 0); CP_COMMIT();
    issue_stage(1, 1); CP_COMMIT();

    for (int c = 0; c < NCHUNK; ++c) {
        const int st = c & 1;
        if (c + 2 < NCHUNK) CP_WAIT1(); else CP_WAIT0();
        __syncthreads();

        const uint32_t sA_hi = base_u + st * STAGE_BY;
        const uint32_t sA_lo = sA_hi + TILE_BY;
        const uint32_t sB_hi = sA_hi + 2 * TILE_BY;
        const uint32_t sB_lo = sA_hi + 3 * TILE_BY;

        #pragma unroll
        for (int ks = 0; ks < 2; ++ks) {
            uint32_t ah[2][4], al[2][4], bh[8][2], bl[8][2];
            #pragma unroll
            for (int mf = 0; mf < 2; ++mf) {
                uint32_t ra = (arow + mf * 16) * ROW_B + ks * 32 + akof;
                LDSM_X4(ah[mf][0], ah[mf][1], ah[mf][2], ah[mf][3], sA_hi + ra);
                LDSM_X4(al[mf][0], al[mf][1], al[mf][2], al[mf][3], sA_lo + ra);
            }
            #pragma unroll
            for (int ng = 0; ng < 4; ++ng) {
                uint32_t rb = (brow + ng * 16) * ROW_B + ks * 32 + bkof;
                LDSM_X4(bh[ng*2][0], bh[ng*2][1], bh[ng*2+1][0], bh[ng*2+1][1], sB_hi + rb);
                LDSM_X4(bl[ng*2][0], bl[ng*2][1], bl[ng*2+1][0], bl[ng*2+1][1], sB_lo + rb);
            }
            #pragma unroll
            for (int mf = 0; mf < 2; ++mf)
                #pragma unroll
                for (int nf = 0; nf < 8; ++nf) {
                    MMA16816(acc[mf][nf], ah[mf][0], ah[mf][1], ah[mf][2], ah[mf][3],
                             bh[nf][0], bh[nf][1]);
                    MMA16816(acc[mf][nf], ah[mf][0], ah[mf][1], ah[mf][2], ah[mf][3],
                             bl[nf][0], bl[nf][1]);
                    MMA16816(acc[mf][nf], al[mf][0], al[mf][1], al[mf][2], al[mf][3],
                             bh[nf][0], bh[nf][1]);
                }
        }
        __syncthreads();
        if (c + 2 < NCHUNK) { issue_stage(c + 2, st); CP_COMMIT(); }
    }

    // Epilogue: c-fragment m16n8 -> lane holds (m=l/4, n=2(l%4)) and (m+8)
    const int mrow = lane >> 2;
    const int ncol = (lane & 3) * 2;
    #pragma unroll
    for (int mf = 0; mf < 2; ++mf) {
        #pragma unroll
        for (int nf = 0; nf < 8; ++nf) {
            int m = m0 + wm * 32 + mf * 16 + mrow;
            int n = n0 + wn * 64 + nf * 8 + ncol;
            float b0 = bias[n], b1 = bias[n + 1];
            float2 lo = make_float2(acc[mf][nf][0] + b0, acc[mf][nf][1] + b1);
            float2 hi = make_float2(acc[mf][nf][2] + b0, acc[mf][nf][3] + b1);
            if (SCATTER) {
                int b  = m >> 11, s = m & (SS - 1);
                int h  = n >> 6,  d = n & (DH - 1);
                int b2 = (m + 8) >> 11, s2 = (m + 8) & (SS - 1);
                *(float2*)&C[(((size_t)(b  * HH + h)) * SS + s ) * DH + d] = lo;
                *(float2*)&C[(((size_t)(b2 * HH + h)) * SS + s2) * DH + d] = hi;
            } else {
                *(float2*)&C[(size_t)m * DD + n]       = lo;
                *(float2*)&C[(size_t)(m + 8) * DD + n] = hi;
            }
        }
    }
}

__global__ void __launch_bounds__(256)
qkv_mma_kernel(const float* __restrict__ bq, const float* __restrict__ bk,
               const float* __restrict__ bv) {
    int z = blockIdx.z;
    float* out = (z == 0) ? g_q : (z == 1) ? g_k : g_v;
    const float* bias = (z == 0) ? bq : (z == 1) ? bk : bv;
    mma_gemm_body<1>(g_x_hi, g_x_lo,
                     g_wt_hi + (size_t)z * DD * DD, g_wt_lo + (size_t)z * DD * DD,
                     bias, out);
}

__global__ void __launch_bounds__(256)
outproj_mma_kernel(const float* __restrict__ bo, float* __restrict__ out) {
    mma_gemm_body<0>(g_at_hi, g_at_lo,
                     g_wt_hi + (size_t)3 * DD * DD, g_wt_lo + (size_t)3 * DD * DD,
                     bo, out);
}

// ---------------------------------------------------------------------------
// Flash-style causal attention (unchanged from R1 - known good)
// ---------------------------------------------------------------------------
#define QS_STRIDE 68
#define KT_STRIDE 65
#define VS_STRIDE 68
#define SS_STRIDE 65

__global__ void __launch_bounds__(256)
attn_kernel()
{
    extern __shared__ float sm[];
    float* Qs  = sm;
    float* KsT = Qs  + 64 * QS_STRIDE;
    float* Vs  = KsT + 64 * KT_STRIDE;
    float* Sc  = Vs  + 64 * VS_STRIDE;

    const int tid = threadIdx.x;
    const int bh  = blockIdx.y;
    const int qt  = blockIdx.x;
    const int q0  = qt * 64;

    const float* Qp = g_q + (size_t)bh * SS * DH;
    const float* Kp = g_k + (size_t)bh * SS * DH;
    const float* Vp = g_v + (size_t)bh * SS * DH;

    const int stx = (tid & 15) * 4;
    const int sty = (tid >> 4) * 4;
    const int r  = tid >> 2;
    const int gc = (tid & 3) * 16;

    #pragma unroll
    for (int it = 0; it < 4; ++it) {
        int idx = tid + it * 256;
        int rr = idx >> 4;
        int c4 = (idx & 15) * 4;
        *(float4*)&Qs[rr * QS_STRIDE + c4] =
            *(const float4*)(Qp + (size_t)(q0 + rr) * DH + c4);
    }

    float m_run = -1e30f, l_run = 0.f;
    float o[16];
    #pragma unroll
    for (int i = 0; i < 16; ++i) o[i] = 0.f;

    for (int kt = 0; kt <= qt; ++kt) {
        const int t0 = kt * 64;
        __syncthreads();

        #pragma unroll
        for (int it = 0; it < 4; ++it) {
            int idx = tid + it * 256;
            int rr  = idx >> 4;
            int c4  = (idx & 15) * 4;
            float4 kv = *(const float4*)(Kp + (size_t)(t0 + rr) * DH + c4);
            KsT[(c4 + 0) * KT_STRIDE + rr] = kv.x;
            KsT[(c4 + 1) * KT_STRIDE + rr] = kv.y;
            KsT[(c4 + 2) * KT_STRIDE + rr] = kv.z;
            KsT[(c4 + 3) * KT_STRIDE + rr] = kv.w;
            *(float4*)&Vs[rr * VS_STRIDE + c4] =
                *(const float4*)(Vp + (size_t)(t0 + rr) * DH + c4);
        }
        __syncthreads();

        {
            float acc[4][4];
            #pragma unroll
            for (int i = 0; i < 4; ++i)
                #pragma unroll
                for (int j = 0; j < 4; ++j) acc[i][j] = 0.f;

            #pragma unroll 4
            for (int d = 0; d < 64; ++d) {
                float a[4], b[4];
                #pragma unroll
                for (int i = 0; i < 4; ++i) a[i] = Qs[(sty + i) * QS_STRIDE + d];
                #pragma unroll
                for (int j = 0; j < 4; ++j) b[j] = KsT[d * KT_STRIDE + stx + j];
                #pragma unroll
                for (int i = 0; i < 4; ++i)
                    #pragma unroll
                    for (int j = 0; j < 4; ++j)
                        acc[i][j] = fmaf(a[i], b[j], acc[i][j]);
            }
            #pragma unroll
            for (int i = 0; i < 4; ++i)
                #pragma unroll
                for (int j = 0; j < 4; ++j)
                    Sc[(sty + i) * SS_STRIDE + stx + j] = acc[i][j];
        }
        __syncthreads();

        {
            float sv[16];
            float mloc = -1e30f;
            #pragma unroll
            for (int cc = 0; cc < 16; ++cc) {
                int j = gc + cc;
                float s = Sc[r * SS_STRIDE + j] * 0.125f;
                if (t0 + j > q0 + r) s = -1e30f;
                sv[cc] = s;
                mloc = fmaxf(mloc, s);
            }
            mloc = fmaxf(mloc, __shfl_xor_sync(0xffffffffu, mloc, 1));
            mloc = fmaxf(mloc, __shfl_xor_sync(0xffffffffu, mloc, 2));

            float m_new = fmaxf(m_run, mloc);
            float corr  = __expf(m_run - m_new);
            float psum  = 0.f;
            #pragma unroll
            for (int cc = 0; cc < 16; ++cc) {
                float p = __expf(sv[cc] - m_new);
                Sc[r * SS_STRIDE + gc + cc] = p;
                psum += p;
            }
            psum += __shfl_xor_sync(0xffffffffu, psum, 1);
            psum += __shfl_xor_sync(0xffffffffu, psum, 2);

            l_run = l_run * corr + psum;
            m_run = m_new;
            #pragma unroll
            for (int cc = 0; cc < 16; ++cc) o[cc] *= corr;
        }
        __syncthreads();

        #pragma unroll 2
        for (int j = 0; j < 64; ++j) {
            float p = Sc[r * SS_STRIDE + j];
            const float* vrow = &Vs[j * VS_STRIDE + gc];
            float4 v0 = *(const float4*)(vrow + 0);
            float4 v1 = *(const float4*)(vrow + 4);
            float4 v2 = *(const float4*)(vrow + 8);
            float4 v3 = *(const float4*)(vrow + 12);
            o[0]  = fmaf(p, v0.x, o[0]);  o[1]  = fmaf(p, v0.y, o[1]);
            o[2]  = fmaf(p, v0.z, o[2]);  o[3]  = fmaf(p, v0.w, o[3]);
            o[4]  = fmaf(p, v1.x, o[4]);  o[5]  = fmaf(p, v1.y, o[5]);
            o[6]  = fmaf(p, v1.z, o[6]);  o[7]  = fmaf(p, v1.w, o[7]);
            o[8]  = fmaf(p, v2.x, o[8]);  o[9]  = fmaf(p, v2.y, o[9]);
            o[10] = fmaf(p, v2.z, o[10]); o[11] = fmaf(p, v2.w, o[11]);
            o[12] = fmaf(p, v3.x, o[12]); o[13] = fmaf(p, v3.y, o[13]);
            o[14] = fmaf(p, v3.z, o[14]); o[15] = fmaf(p, v3.w, o[15]);
        }
    }

    {
        float inv = 1.f / l_run;
        int b = bh >> 4;
        int h = bh & (HH - 1);
        size_t base = ((size_t)(b * SS + q0 + r)) * DD + h * DH + gc;
        float4 w0 = make_float4(o[0] * inv,  o[1] * inv,  o[2] * inv,  o[3] * inv);
        float4 w1 = make_float4(o[4] * inv,  o[5] * inv,  o[6] * inv,  o[7] * inv);
        float4 w2 = make_float4(o[8] * inv,  o[9] * inv,  o[10] * inv, o[11] * inv);
        float4 w3 = make_float4(o[12] * inv, o[13] * inv, o[14] * inv, o[15] * inv);
        *(float4*)&g_attn[base + 0]  = w0;
        *(float4*)&g_attn[base + 4]  = w1;
        *(float4*)&g_attn[base + 8]  = w2;
        *(float4*)&g_attn[base + 12] = w3;
    }
}

// ---------------------------------------------------------------------------
extern "C" void kernel_launch(void* const* d_in, const int* in_sizes, int n_in,
                              void* d_out, int out_size)
{
    const float* x  = (const float*)d_in[0];
    const float* Wq = (const float*)d_in[1];
    const float* bq = (const float*)d_in[2];
    const float* Wk = (const float*)d_in[3];
    const float* bk = (const float*)d_in[4];
    const float* Wv = (const float*)d_in[5];
    const float* bv = (const float*)d_in[6];
    const float* Wo = (const float*)d_in[7];
    const float* bo = (const float*)d_in[8];
    float* out = (float*)d_out;

    cudaFuncSetAttribute(qkv_mma_kernel,
                         cudaFuncAttributeMaxDynamicSharedMemorySize, SMEM_MMA);
    cudaFuncSetAttribute(outproj_mma_kernel,
                         cudaFuncAttributeMaxDynamicSharedMemorySize, SMEM_MMA);
    int attn_smem = (64 * QS_STRIDE + 64 * KT_STRIDE +
                     64 * VS_STRIDE + 64 * SS_STRIDE) * (int)sizeof(float);
    cudaFuncSetAttribute(attn_kernel,
                         cudaFuncAttributeMaxDynamicSharedMemorySize, attn_smem);

    // 1) split x, transpose+split weights
    {
        __nv_bfloat16 *xh, *xl;
        cudaGetSymbolAddress((void**)&xh, g_x_hi);
        cudaGetSymbolAddress((void**)&xl, g_x_lo);
        split_kernel<<<(MROWS * DD) / (256 * 4), 256>>>(x, xh, xl);
        transpose_split_w<<<dim3(32, 32, 4), dim3(32, 8)>>>(Wq, Wk, Wv, Wo);
    }

    // 2) QKV projections (HMMA split-bf16)
    qkv_mma_kernel<<<dim3(DD / 128, MROWS / 128, 3), 256, SMEM_MMA>>>(bq, bk, bv);

    // 3) causal attention
    attn_kernel<<<dim3(SS / 64, BB * HH), 256, attn_smem>>>();

    // 4) split attention output, then output projection
    {
        float* at; __nv_bfloat16 *ah, *al;
        cudaGetSymbolAddress((void**)&at, g_attn);
        cudaGetSymbolAddress((void**)&ah, g_at_hi);
        cudaGetSymbolAddress((void**)&al, g_at_lo);
        split_kernel<<<(MROWS * DD) / (256 * 4), 256>>>(at, ah, al);
    }
    outproj_mma_kernel<<<dim3(DD / 128, MROWS / 128), 256, SMEM_MMA>>>(bo, out);
}

// round 4
// speedup vs baseline: 4.5424x; 3.6482x over previous
#include <cuda_runtime.h>
#include <cuda_bf16.h>
#include <cstdint>
#include <math.h>
#include <string.h>

// Problem shape (fixed)
#define BB 4
#define SS 2048
#define DD 1024
#define HH 16
#define DH 64
#define MROWS (BB*SS)   // 8192

// ---------------------------------------------------------------------------
// Scratch (__device__ globals; allocation-free rule). All bf16 hi/lo pairs.
// q/k/v layout: [B*H][S][64]
// ---------------------------------------------------------------------------
__device__ __nv_bfloat16 g_qh[(size_t)BB*HH*SS*DH];
__device__ __nv_bfloat16 g_ql[(size_t)BB*HH*SS*DH];
__device__ __nv_bfloat16 g_kh[(size_t)BB*HH*SS*DH];
__device__ __nv_bfloat16 g_kl[(size_t)BB*HH*SS*DH];
__device__ __nv_bfloat16 g_vh[(size_t)BB*HH*SS*DH];
__device__ __nv_bfloat16 g_vl[(size_t)BB*HH*SS*DH];

__device__ __nv_bfloat16 g_x_hi[(size_t)MROWS*DD];
__device__ __nv_bfloat16 g_x_lo[(size_t)MROWS*DD];
__device__ __nv_bfloat16 g_at_hi[(size_t)MROWS*DD];
__device__ __nv_bfloat16 g_at_lo[(size_t)MROWS*DD];
// transposed+split weights: [4][N][K], Wt[n][k] = W[k][n]; 0..3 = q,k,v,o
__device__ __nv_bfloat16 g_wt_hi[(size_t)4*DD*DD];
__device__ __nv_bfloat16 g_wt_lo[(size_t)4*DD*DD];

// ---------------------------------------------------------------------------
// Helpers (base-sm_103-safe: no tcgen05 anywhere)
// ---------------------------------------------------------------------------
__device__ __forceinline__ uint32_t smem_u32(const void* p) {
    uint32_t a;
    asm("{ .reg .u64 t; cvta.to.shared.u64 t, %1; cvt.u32.u64 %0, t; }"
        : "=r"(a) : "l"(p));
    return a;
}
#define CP_ASYNC16(dst_u32, src_ptr) \
    asm volatile("cp.async.cg.shared.global [%0], [%1], 16;" \
                 :: "r"(dst_u32), "l"(src_ptr))
#define CP_COMMIT() asm volatile("cp.async.commit_group;")
#define CP_WAIT1()  asm volatile("cp.async.wait_group 1;")
#define CP_WAIT0()  asm volatile("cp.async.wait_group 0;")

#define LDSM_X4(r0, r1, r2, r3, addr) \
    asm volatile("ldmatrix.sync.aligned.m8n8.x4.shared.b16 {%0,%1,%2,%3}, [%4];" \
                 : "=r"(r0), "=r"(r1), "=r"(r2), "=r"(r3) : "r"(addr))
#define LDSM_X4_T(r0, r1, r2, r3, addr) \
    asm volatile("ldmatrix.sync.aligned.m8n8.x4.trans.shared.b16 {%0,%1,%2,%3}, [%4];" \
                 : "=r"(r0), "=r"(r1), "=r"(r2), "=r"(r3) : "r"(addr))

#define MMA16816(d, a0, a1, a2, a3, b0, b1) \
    asm volatile("mma.sync.aligned.m16n8k16.row.col.f32.bf16.bf16.f32 " \
                 "{%0,%1,%2,%3}, {%4,%5,%6,%7}, {%8,%9}, {%0,%1,%2,%3};" \
                 : "+f"((d)[0]), "+f"((d)[1]), "+f"((d)[2]), "+f"((d)[3]) \
                 : "r"(a0), "r"(a1), "r"(a2), "r"(a3), "r"(b0), "r"(b1))

__device__ __forceinline__ uint32_t pack_bf2(__nv_bfloat16 a, __nv_bfloat16 b) {
    __nv_bfloat162 h; h.x = a; h.y = b;
    uint32_t u; memcpy(&u, &h, 4);
    return u;
}

// ---------------------------------------------------------------------------
// Prep kernels
// ---------------------------------------------------------------------------
__global__ void __launch_bounds__(256)
split_kernel(const float* __restrict__ in, __nv_bfloat16* __restrict__ hi,
             __nv_bfloat16* __restrict__ lo) {
    size_t i = ((size_t)blockIdx.x * 256 + threadIdx.x) * 4;
    float4 v = *(const float4*)(in + i);
    __nv_bfloat16 h0 = __float2bfloat16(v.x);
    __nv_bfloat16 h1 = __float2bfloat16(v.y);
    __nv_bfloat16 h2 = __float2bfloat16(v.z);
    __nv_bfloat16 h3 = __float2bfloat16(v.w);
    *(uint32_t*)(hi + i)     = pack_bf2(h0, h1);
    *(uint32_t*)(hi + i + 2) = pack_bf2(h2, h3);
    *(uint32_t*)(lo + i)     = pack_bf2(__float2bfloat16(v.x - __bfloat162float(h0)),
                                        __float2bfloat16(v.y - __bfloat162float(h1)));
    *(uint32_t*)(lo + i + 2) = pack_bf2(__float2bfloat16(v.z - __bfloat162float(h2)),
                                        __float2bfloat16(v.w - __bfloat162float(h3)));
}

__global__ void __launch_bounds__(256)
transpose_split_w(const float* __restrict__ Wq, const float* __restrict__ Wk,
                  const float* __restrict__ Wv, const float* __restrict__ Wo) {
    __shared__ float t[32][33];
    const float* W = (blockIdx.z == 0) ? Wq : (blockIdx.z == 1) ? Wk :
                     (blockIdx.z == 2) ? Wv : Wo;
    __nv_bfloat16* Th = g_wt_hi + (size_t)blockIdx.z * DD * DD;
    __nv_bfloat16* Tl = g_wt_lo + (size_t)blockIdx.z * DD * DD;
    int k0 = blockIdx.y * 32, n0 = blockIdx.x * 32;
    int tx = threadIdx.x, ty = threadIdx.y;
    #pragma unroll
    for (int i = ty; i < 32; i += 8)
        t[i][tx] = W[(size_t)(k0 + i) * DD + n0 + tx];
    __syncthreads();
    #pragma unroll
    for (int i = ty; i < 32; i += 8) {
        float v = t[tx][i];               // W[k0+tx][n0+i]
        size_t o = (size_t)(n0 + i) * DD + k0 + tx;
        __nv_bfloat16 h = __float2bfloat16(v);
        Th[o] = h;
        Tl[o] = __float2bfloat16(v - __bfloat162float(h));
    }
}

// ---------------------------------------------------------------------------
// Split-bf16 GEMM on mma.sync. MODE 0: fp32 out [M][N]. MODE 1: bf16 hi/lo
// split-scatter into [B*H][S][64] with optional scale.
// ---------------------------------------------------------------------------
#define KC 32
#define NCHUNK (DD / KC)              // 32
#define ROW_B 80
#define TILE_BY (128 * ROW_B)
#define STAGE_BY (4 * TILE_BY)
#define SMEM_MMA (2 * STAGE_BY)       // 81920

template<int MODE>
__device__ __forceinline__ void mma_gemm_body(const __nv_bfloat16* __restrict__ Ah,
                                              const __nv_bfloat16* __restrict__ Al,
                                              const __nv_bfloat16* __restrict__ Bh,
                                              const __nv_bfloat16* __restrict__ Bl,
                                              const float* __restrict__ bias,
                                              float* __restrict__ C,
                                              __nv_bfloat16* __restrict__ Hi,
                                              __nv_bfloat16* __restrict__ Lo,
                                              float scale)
{
    extern __shared__ char dynsmem[];
    const uint32_t base_u = smem_u32(dynsmem);

    const int tid  = threadIdx.x;
    const int wid  = tid >> 5, lane = tid & 31;
    const int wm   = wid & 3;
    const int wn   = wid >> 2;
    const int m0   = blockIdx.y * 128;
    const int n0   = blockIdx.x * 128;

    const __nv_bfloat16* srcs[4] = { Ah, Al, Bh, Bl };
    const int rowbase[4] = { m0, m0, n0, n0 };

    auto issue_stage = [&](int c, int st) {
        #pragma unroll
        for (int tile = 0; tile < 4; ++tile) {
            const __nv_bfloat16* src = srcs[tile] + (size_t)rowbase[tile] * DD + c * KC;
            uint32_t dst = base_u + st * STAGE_BY + tile * TILE_BY;
            #pragma unroll
            for (int it = 0; it < 2; ++it) {
                int idx = tid + it * 256;
                int row = idx >> 2;
                int seg = idx & 3;
                CP_ASYNC16(dst + row * ROW_B + seg * 16,
                           src + (size_t)row * DD + seg * 8);
            }
        }
    };

    float acc[2][8][4];
    #pragma unroll
    for (int i = 0; i < 2; ++i)
        #pragma unroll
        for (int j = 0; j < 8; ++j)
            #pragma unroll
            for (int q = 0; q < 4; ++q) acc[i][j][q] = 0.f;

    const int arow = wm * 32 + (lane & 15);
    const int akof = ((lane >> 4) & 1) * 16;
    const int brow = wn * 64 + (lane & 7) + ((lane >> 4) & 1) * 8;
    const int bkof = ((lane >> 3) & 1) * 16;

    issue_stage(0, 0); CP_COMMIT();
    issue_stage(1, 1); CP_COMMIT();

    for (int c = 0; c < NCHUNK; ++c) {
        const int st = c & 1;
        if (c + 2 < NCHUNK) CP_WAIT1(); else CP_WAIT0();
        __syncthreads();

        const uint32_t sA_hi = base_u + st * STAGE_BY;
        const uint32_t sA_lo = sA_hi + TILE_BY;
        const uint32_t sB_hi = sA_hi + 2 * TILE_BY;
        const uint32_t sB_lo = sA_hi + 3 * TILE_BY;

        #pragma unroll
        for (int ks = 0; ks < 2; ++ks) {
            uint32_t ah[2][4], al[2][4], bh[8][2], bl[8][2];
            #pragma unroll
            for (int mf = 0; mf < 2; ++mf) {
                uint32_t ra = (arow + mf * 16) * ROW_B + ks * 32 + akof;
                LDSM_X4(ah[mf][0], ah[mf][1], ah[mf][2], ah[mf][3], sA_hi + ra);
                LDSM_X4(al[mf][0], al[mf][1], al[mf][2], al[mf][3], sA_lo + ra);
            }
            #pragma unroll
            for (int ng = 0; ng < 4; ++ng) {
                uint32_t rb = (brow + ng * 16) * ROW_B + ks * 32 + bkof;
                LDSM_X4(bh[ng*2][0], bh[ng*2][1], bh[ng*2+1][0], bh[ng*2+1][1], sB_hi + rb);
                LDSM_X4(bl[ng*2][0], bl[ng*2][1], bl[ng*2+1][0], bl[ng*2+1][1], sB_lo + rb);
            }
            #pragma unroll
            for (int mf = 0; mf < 2; ++mf)
                #pragma unroll
                for (int nf = 0; nf < 8; ++nf) {
                    MMA16816(acc[mf][nf], ah[mf][0], ah[mf][1], ah[mf][2], ah[mf][3],
                             bh[nf][0], bh[nf][1]);
                    MMA16816(acc[mf][nf], ah[mf][0], ah[mf][1], ah[mf][2], ah[mf][3],
                             bl[nf][0], bl[nf][1]);
                    MMA16816(acc[mf][nf], al[mf][0], al[mf][1], al[mf][2], al[mf][3],
                             bh[nf][0], bh[nf][1]);
                }
        }
        __syncthreads();
        if (c + 2 < NCHUNK) { issue_stage(c + 2, st); CP_COMMIT(); }
    }

    const int mrow = lane >> 2;
    const int ncol = (lane & 3) * 2;
    #pragma unroll
    for (int mf = 0; mf < 2; ++mf) {
        #pragma unroll
        for (int nf = 0; nf < 8; ++nf) {
            int m = m0 + wm * 32 + mf * 16 + mrow;
            int n = n0 + wn * 64 + nf * 8 + ncol;
            float b0 = bias[n], b1 = bias[n + 1];
            float v00 = (acc[mf][nf][0] + b0) * scale;
            float v01 = (acc[mf][nf][1] + b1) * scale;
            float v10 = (acc[mf][nf][2] + b0) * scale;
            float v11 = (acc[mf][nf][3] + b1) * scale;
            if (MODE == 0) {
                *(float2*)&C[(size_t)m * DD + n]       = make_float2(v00, v01);
                *(float2*)&C[(size_t)(m + 8) * DD + n] = make_float2(v10, v11);
            } else {
                int b = m >> 11, h = n >> 6, d = n & 63;
                int s  = m & (SS - 1);
                size_t o0 = (((size_t)(b * HH + h)) * SS + s) * DH + d;
                size_t o1 = o0 + 8 * DH;
                __nv_bfloat16 h00 = __float2bfloat16(v00), h01 = __float2bfloat16(v01);
                __nv_bfloat16 h10 = __float2bfloat16(v10), h11 = __float2bfloat16(v11);
                *(uint32_t*)(Hi + o0) = pack_bf2(h00, h01);
                *(uint32_t*)(Hi + o1) = pack_bf2(h10, h11);
                *(uint32_t*)(Lo + o0) = pack_bf2(
                    __float2bfloat16(v00 - __bfloat162float(h00)),
                    __float2bfloat16(v01 - __bfloat162float(h01)));
                *(uint32_t*)(Lo + o1) = pack_bf2(
                    __float2bfloat16(v10 - __bfloat162float(h10)),
                    __float2bfloat16(v11 - __bfloat162float(h11)));
            }
        }
    }
}

__global__ void __launch_bounds__(256)
qkv_mma_kernel(const float* __restrict__ bq, const float* __restrict__ bk,
               const float* __restrict__ bv) {
    int z = blockIdx.z;
    __nv_bfloat16* Hi = (z == 0) ? g_qh : (z == 1) ? g_kh : g_vh;
    __nv_bfloat16* Lo = (z == 0) ? g_ql : (z == 1) ? g_kl : g_vl;
    const float* bias = (z == 0) ? bq : (z == 1) ? bk : bv;
    float scale = (z == 0) ? 0.125f : 1.0f;   // fold 1/sqrt(Dh) into q (exact)
    mma_gemm_body<1>(g_x_hi, g_x_lo,
                     g_wt_hi + (size_t)z * DD * DD, g_wt_lo + (size_t)z * DD * DD,
                     bias, nullptr, Hi, Lo, scale);
}

__global__ void __launch_bounds__(256)
outproj_mma_kernel(const float* __restrict__ bo, float* __restrict__ out) {
    mma_gemm_body<0>(g_at_hi, g_at_lo,
                     g_wt_hi + (size_t)3 * DD * DD, g_wt_lo + (size_t)3 * DD * DD,
                     bo, out, nullptr, nullptr, 1.0f);
}

// ---------------------------------------------------------------------------
// Tensor-core flash attention (split-bf16, causal).
// CTA: 128 Q rows x 64 KV tile, 8 warps (16 Q rows each), 256 threads.
// smem: Qh,Ql [128][72]bf16 persistent; 2-stage KV (Kh,Kl,Vh,Vl [64][72]).
// ---------------------------------------------------------------------------
#define AROWB 144                     // 64 bf16 + 8 pad = 144 bytes/row
#define ATILE_BY (64 * AROWB)         // 9216
#define AQ_BY (128 * AROWB)           // 18432
#define ASTAGE_BY (4 * ATILE_BY)      // 36864
#define SMEM_ATT (2 * AQ_BY + 2 * ASTAGE_BY)   // 110592

__global__ void __launch_bounds__(256, 2)
attn_mma_kernel()
{
    extern __shared__ char dynsmem[];
    const uint32_t base_u = smem_u32(dynsmem);
    const uint32_t sQh = base_u;
    const uint32_t sQl = base_u + AQ_BY;
    const uint32_t kvb = base_u + 2 * AQ_BY;

    const int tid  = threadIdx.x;
    const int w    = tid >> 5, lane = tid & 31;
    const int bh   = blockIdx.y;
    const int qt   = (int)(gridDim.x - 1 - blockIdx.x);   // heavy tiles first
    const int q0   = qt * 128;
    const int nt   = 2 * qt + 2;

    const size_t hb = (size_t)bh * SS * DH;
    const __nv_bfloat16* qh = g_qh + hb;
    const __nv_bfloat16* ql = g_ql + hb;
    const __nv_bfloat16* kh = g_kh + hb;
    const __nv_bfloat16* kl = g_kl + hb;
    const __nv_bfloat16* vh = g_vh + hb;
    const __nv_bfloat16* vl = g_vl + hb;

    // --- async loads ---
    auto load_q = [&]() {
        #pragma unroll
        for (int it = 0; it < 4; ++it) {
            int idx = tid + it * 256;       // 0..1023
            int row = idx >> 3, seg = idx & 7;
            CP_ASYNC16(sQh + row * AROWB + seg * 16, qh + (size_t)(q0 + row) * DH + seg * 8);
            CP_ASYNC16(sQl + row * AROWB + seg * 16, ql + (size_t)(q0 + row) * DH + seg * 8);
        }
    };
    auto issue_kv = [&](int kt, int st) {
        const int t0 = kt * 64;
        const __nv_bfloat16* srcs[4] = { kh, kl, vh, vl };
        uint32_t sb = kvb + st * ASTAGE_BY;
        #pragma unroll
        for (int tile = 0; tile < 4; ++tile) {
            const __nv_bfloat16* src = srcs[tile] + (size_t)t0 * DH;
            uint32_t dst = sb + tile * ATILE_BY;
            #pragma unroll
            for (int it = 0; it < 2; ++it) {
                int idx = tid + it * 256;   // 0..511
                int row = idx >> 3, seg = idx & 7;
                CP_ASYNC16(dst + row * AROWB + seg * 16, src + (size_t)row * DH + seg * 8);
            }
        }
    };

    load_q(); issue_kv(0, 0); CP_COMMIT();
    if (nt > 1) { issue_kv(1, 1); }
    CP_COMMIT();

    float Oa[8][4];
    #pragma unroll
    for (int i = 0; i < 8; ++i)
        #pragma unroll
        for (int j = 0; j < 4; ++j) Oa[i][j] = 0.f;
    float m_run0 = -1e30f, m_run1 = -1e30f, l_run0 = 0.f, l_run1 = 0.f;

    // ldmatrix address components
    const uint32_t qoffA = (uint32_t)(16 * w + (lane & 15)) * AROWB + ((lane >> 4) & 1) * 16;
    const int krow = (lane & 7) + ((lane >> 4) & 1) * 8;
    const int kkof = ((lane >> 3) & 1) * 16;
    const int vrow = ((lane >> 3) & 1) * 8 + (lane & 7);
    const int vcof = ((lane >> 4) & 1) * 8;

    for (int kt = 0; kt < nt; ++kt) {
        const int st = kt & 1;
        const int t0 = kt * 64;
        if (kt + 1 < nt) CP_WAIT1(); else CP_WAIT0();
        __syncthreads();

        const uint32_t sK = kvb + st * ASTAGE_BY;
        const uint32_t sV = sK + 2 * ATILE_BY;

        // ---- S = Qh*Kh + Qh*Kl + Ql*Kh ----
        float acc[8][4];
        #pragma unroll
        for (int i = 0; i < 8; ++i)
            #pragma unroll
            for (int j = 0; j < 4; ++j) acc[i][j] = 0.f;

        #pragma unroll
        for (int ks = 0; ks < 4; ++ks) {
            uint32_t qa = qoffA + ks * 32;
            uint32_t aH[4], aL[4];
            LDSM_X4(aH[0], aH[1], aH[2], aH[3], sQh + qa);
            LDSM_X4(aL[0], aL[1], aL[2], aL[3], sQl + qa);
            #pragma unroll
            for (int ng = 0; ng < 4; ++ng) {
                uint32_t kb = sK + (uint32_t)(16 * ng + krow) * AROWB + ks * 32 + kkof;
                uint32_t kH[4], kL[4];
                LDSM_X4(kH[0], kH[1], kH[2], kH[3], kb);
                LDSM_X4(kL[0], kL[1], kL[2], kL[3], kb + ATILE_BY);
                MMA16816(acc[2*ng],   aH[0], aH[1], aH[2], aH[3], kH[0], kH[1]);
                MMA16816(acc[2*ng],   aH[0], aH[1], aH[2], aH[3], kL[0], kL[1]);
                MMA16816(acc[2*ng],   aL[0], aL[1], aL[2], aL[3], kH[0], kH[1]);
                MMA16816(acc[2*ng+1], aH[0], aH[1], aH[2], aH[3], kH[2], kH[3]);
                MMA16816(acc[2*ng+1], aH[0], aH[1], aH[2], aH[3], kL[2], kL[3]);
                MMA16816(acc[2*ng+1], aL[0], aL[1], aL[2], aL[3], kH[2], kH[3]);
            }
        }

        // ---- causal mask (only diagonal region) ----
        if (kt >= 2 * qt) {
            int rb = q0 + 16 * w + (lane >> 2);
            int cb = t0 + 2 * (lane & 3);
            #pragma unroll
            for (int nf = 0; nf < 8; ++nf) {
                int c0 = cb + 8 * nf;
                if (c0     > rb)     acc[nf][0] = -1e30f;
                if (c0 + 1 > rb)     acc[nf][1] = -1e30f;
                if (c0     > rb + 8) acc[nf][2] = -1e30f;
                if (c0 + 1 > rb + 8) acc[nf][3] = -1e30f;
            }
        }

        // ---- online softmax ----
        float mx0 = -1e30f, mx1 = -1e30f;
        #pragma unroll
        for (int nf = 0; nf < 8; ++nf) {
            mx0 = fmaxf(mx0, fmaxf(acc[nf][0], acc[nf][1]));
            mx1 = fmaxf(mx1, fmaxf(acc[nf][2], acc[nf][3]));
        }
        mx0 = fmaxf(mx0, __shfl_xor_sync(0xffffffffu, mx0, 1));
        mx0 = fmaxf(mx0, __shfl_xor_sync(0xffffffffu, mx0, 2));
        mx1 = fmaxf(mx1, __shfl_xor_sync(0xffffffffu, mx1, 1));
        mx1 = fmaxf(mx1, __shfl_xor_sync(0xffffffffu, mx1, 2));

        float mn0 = fmaxf(m_run0, mx0), mn1 = fmaxf(m_run1, mx1);
        float corr0 = __expf(m_run0 - mn0), corr1 = __expf(m_run1 - mn1);

        uint32_t pH[8][2], pL[8][2];
        float s0 = 0.f, s1 = 0.f;
        #pragma unroll
        for (int nf = 0; nf < 8; ++nf) {
            float p00 = __expf(acc[nf][0] - mn0);
            float p01 = __expf(acc[nf][1] - mn0);
            float p10 = __expf(acc[nf][2] - mn1);
            float p11 = __expf(acc[nf][3] - mn1);
            s0 += p00 + p01; s1 += p10 + p11;
            __nv_bfloat16 h00 = __float2bfloat16(p00), h01 = __float2bfloat16(p01);
            __nv_bfloat16 h10 = __float2bfloat16(p10), h11 = __float2bfloat16(p11);
            pH[nf][0] = pack_bf2(h00, h01);
            pH[nf][1] = pack_bf2(h10, h11);
            pL[nf][0] = pack_bf2(__float2bfloat16(p00 - __bfloat162float(h00)),
                                 __float2bfloat16(p01 - __bfloat162float(h01)));
            pL[nf][1] = pack_bf2(__float2bfloat16(p10 - __bfloat162float(h10)),
                                 __float2bfloat16(p11 - __bfloat162float(h11)));
        }
        s0 += __shfl_xor_sync(0xffffffffu, s0, 1);
        s0 += __shfl_xor_sync(0xffffffffu, s0, 2);
        s1 += __shfl_xor_sync(0xffffffffu, s1, 1);
        s1 += __shfl_xor_sync(0xffffffffu, s1, 2);
        l_run0 = l_run0 * corr0 + s0;  m_run0 = mn0;
        l_run1 = l_run1 * corr1 + s1;  m_run1 = mn1;

        #pragma unroll
        for (int nf = 0; nf < 8; ++nf) {
            Oa[nf][0] *= corr0; Oa[nf][1] *= corr0;
            Oa[nf][2] *= corr1; Oa[nf][3] *= corr1;
        }

        // ---- O += Ph*Vh + Ph*Vl + Pl*Vh ----
        #pragma unroll
        for (int kc = 0; kc < 4; ++kc) {
            uint32_t aH0 = pH[2*kc][0],   aH1 = pH[2*kc][1];
            uint32_t aH2 = pH[2*kc+1][0], aH3 = pH[2*kc+1][1];
            uint32_t aL0 = pL[2*kc][0],   aL1 = pL[2*kc][1];
            uint32_t aL2 = pL[2*kc+1][0], aL3 = pL[2*kc+1][1];
            #pragma unroll
            for (int p = 0; p < 4; ++p) {
                uint32_t va = sV + (uint32_t)(16 * kc + vrow) * AROWB + (16 * p + vcof) * 2;
                uint32_t vH[4], vL[4];
                LDSM_X4_T(vH[0], vH[1], vH[2], vH[3], va);
                LDSM_X4_T(vL[0], vL[1], vL[2], vL[3], va + ATILE_BY);
                MMA16816(Oa[2*p],   aH0, aH1, aH2, aH3, vH[0], vH[1]);
                MMA16816(Oa[2*p],   aH0, aH1, aH2, aH3, vL[0], vL[1]);
                MMA16816(Oa[2*p],   aL0, aL1, aL2, aL3, vH[0], vH[1]);
                MMA16816(Oa[2*p+1], aH0, aH1, aH2, aH3, vH[2], vH[3]);
                MMA16816(Oa[2*p+1], aH0, aH1, aH2, aH3, vL[2], vL[3]);
                MMA16816(Oa[2*p+1], aL0, aL1, aL2, aL3, vH[2], vH[3]);
            }
        }

        __syncthreads();
        if (kt + 2 < nt) { issue_kv(kt + 2, st); CP_COMMIT(); }
    }

    // ---- epilogue: write bf16 hi/lo into [M][D] for out projection ----
    float inv0 = 1.f / l_run0, inv1 = 1.f / l_run1;
    int b = bh >> 4, h = bh & (HH - 1);
    int r0 = q0 + 16 * w + (lane >> 2);
    size_t ro0 = (size_t)(b * SS + r0) * DD + h * DH;
    size_t ro1 = ro0 + (size_t)8 * DD;
    #pragma unroll
    for (int nf = 0; nf < 8; ++nf) {
        int d = 8 * nf + 2 * (lane & 3);
        float v00 = Oa[nf][0] * inv0, v01 = Oa[nf][1] * inv0;
        float v10 = Oa[nf][2] * inv1, v11 = Oa[nf][3] * inv1;
        __nv_bfloat16 h00 = __float2bfloat16(v00), h01 = __float2bfloat16(v01);
        __nv_bfloat16 h10 = __float2bfloat16(v10), h11 = __float2bfloat16(v11);
        *(uint32_t*)(g_at_hi + ro0 + d) = pack_bf2(h00, h01);
        *(uint32_t*)(g_at_hi + ro1 + d) = pack_bf2(h10, h11);
        *(uint32_t*)(g_at_lo + ro0 + d) = pack_bf2(
            __float2bfloat16(v00 - __bfloat162float(h00)),
            __float2bfloat16(v01 - __bfloat162float(h01)));
        *(uint32_t*)(g_at_lo + ro1 + d) = pack_bf2(
            __float2bfloat16(v10 - __bfloat162float(h10)),
            __float2bfloat16(v11 - __bfloat162float(h11)));
    }
}

// ---------------------------------------------------------------------------
extern "C" void kernel_launch(void* const* d_in, const int* in_sizes, int n_in,
                              void* d_out, int out_size)
{
    const float* x  = (const float*)d_in[0];
    const float* Wq = (const float*)d_in[1];
    const float* bq = (const float*)d_in[2];
    const float* Wk = (const float*)d_in[3];
    const float* bk = (const float*)d_in[4];
    const float* Wv = (const float*)d_in[5];
    const float* bv = (const float*)d_in[6];
    const float* Wo = (const float*)d_in[7];
    const float* bo = (const float*)d_in[8];
    float* out = (float*)d_out;

    cudaFuncSetAttribute(qkv_mma_kernel,
                         cudaFuncAttributeMaxDynamicSharedMemorySize, SMEM_MMA);
    cudaFuncSetAttribute(outproj_mma_kernel,
                         cudaFuncAttributeMaxDynamicSharedMemorySize, SMEM_MMA);
    cudaFuncSetAttribute(attn_mma_kernel,
                         cudaFuncAttributeMaxDynamicSharedMemorySize, SMEM_ATT);

    // 1) split x, transpose+split weights
    {
        __nv_bfloat16 *xh, *xl;
        cudaGetSymbolAddress((void**)&xh, g_x_hi);
        cudaGetSymbolAddress((void**)&xl, g_x_lo);
        split_kernel<<<(MROWS * DD) / (256 * 4), 256>>>(x, xh, xl);
        transpose_split_w<<<dim3(32, 32, 4), dim3(32, 8)>>>(Wq, Wk, Wv, Wo);
    }

    // 2) QKV projections (HMMA split-bf16, direct bf16 hi/lo epilogue)
    qkv_mma_kernel<<<dim3(DD / 128, MROWS / 128, 3), 256, SMEM_MMA>>>(bq, bk, bv);

    // 3) tensor-core causal flash attention
    attn_mma_kernel<<<dim3(SS / 128, BB * HH), 256, SMEM_ATT>>>();

    // 4) output projection
    outproj_mma_kernel<<<dim3(DD / 128, MROWS / 128), 256, SMEM_MMA>>>(bo, out);
}